// round 1
// baseline (speedup 1.0000x reference)
#include <cuda_runtime.h>
#include <stdint.h>

#define NROWS  65536
#define DIMS   256
#define NCODES 1024
#define TM     64      // rows per block
#define TK     64      // codes per chunk
#define TPAD   68      // padded row stride (floats) for K-major smem tiles

// smem layout (bytes):
//   zs  [DIMS][TPAD] floats : 256*68*4 = 69632
//   es  [DIMS][TPAD] floats : 69632
//   z2s [TM] floats         : 256
//   cand[TM*16] u64         : 8192   (reused as double[256] for loss reduce)
//   idxs[TM] int            : 256
#define SMEM_BYTES (69632 + 69632 + 256 + 8192 + 256)

__device__ float  g_e2[NCODES];
__device__ double g_loss_accum;

// ---------------------------------------------------------------------------
// Kernel A: per-code squared norms + zero the loss accumulator (every replay)
// ---------------------------------------------------------------------------
__global__ void vq_prep(const float* __restrict__ emb) {
    if (blockIdx.x == 0 && threadIdx.x == 0) g_loss_accum = 0.0;
    int warp = (blockIdx.x * blockDim.x + threadIdx.x) >> 5;
    int lane = threadIdx.x & 31;
    if (warp < NCODES) {
        const float* row = emb + warp * DIMS;
        float s = 0.f;
#pragma unroll
        for (int i = 0; i < DIMS / 32; i++) {
            float v = row[lane + 32 * i];
            s = __fadd_rn(s, __fmul_rn(v, v));
        }
#pragma unroll
        for (int o = 16; o > 0; o >>= 1) s = __fadd_rn(s, __shfl_down_sync(0xffffffffu, s, o));
        if (lane == 0) g_e2[warp] = s;
    }
}

// ---------------------------------------------------------------------------
// Main kernel: fused distance GEMM + argmin + gather/STE + loss partial sums
// ---------------------------------------------------------------------------
__global__ void __launch_bounds__(256, 1)
vq_main(const float* __restrict__ z, const float* __restrict__ emb,
        float* __restrict__ out) {
    extern __shared__ char smraw[];
    float* zs  = (float*)smraw;                       // [DIMS][TPAD], K-major
    float* es  = zs + DIMS * TPAD;                    // [DIMS][TPAD], K-major
    float* z2s = es + DIMS * TPAD;                    // [TM]
    unsigned long long* cand = (unsigned long long*)(z2s + TM);  // [TM][16]
    int*    idxs = (int*)(cand + TM * 16);            // [TM]
    double* dred = (double*)cand;                     // reuse for loss reduce

    const int tid = threadIdx.x;
    const int tx  = tid & 15;        // code sub-tile
    const int ty  = tid >> 4;        // row  sub-tile
    const int rowBase = blockIdx.x * TM;
    const float* zblk = z + (size_t)rowBase * DIMS;

    // ---- load z tile, transpose to K-major ----
    for (int i = tid; i < TM * (DIMS / 4); i += 256) {
        int r  = i >> 6;            // 64 float4 per row
        int k4 = i & 63;
        float4 v = ((const float4*)zblk)[(size_t)r * (DIMS / 4) + k4];
        int k = k4 * 4;
        zs[(k + 0) * TPAD + r] = v.x;
        zs[(k + 1) * TPAD + r] = v.y;
        zs[(k + 2) * TPAD + r] = v.z;
        zs[(k + 3) * TPAD + r] = v.w;
    }
    __syncthreads();

    // ---- per-row ||z||^2 (square rounded, then left-to-right sum) ----
    if (tid < TM) {
        float s = 0.f;
        for (int k = 0; k < DIMS; k++) {
            float v = zs[k * TPAD + tid];
            s = __fadd_rn(s, __fmul_rn(v, v));
        }
        z2s[tid] = s;
    }

    unsigned long long best[4];
#pragma unroll
    for (int i = 0; i < 4; i++) best[i] = ~0ull;

    // ---- loop over code chunks ----
    for (int chunk = 0; chunk < NCODES / TK; chunk++) {
        __syncthreads();   // previous chunk's readers done (also covers z2s write)
        const float* eblk = emb + (size_t)chunk * TK * DIMS;
        for (int i = tid; i < TK * (DIMS / 4); i += 256) {
            int c  = i >> 6;
            int k4 = i & 63;
            float4 v = ((const float4*)eblk)[(size_t)c * (DIMS / 4) + k4];
            int k = k4 * 4;
            es[(k + 0) * TPAD + c] = v.x;
            es[(k + 1) * TPAD + c] = v.y;
            es[(k + 2) * TPAD + c] = v.z;
            es[(k + 3) * TPAD + c] = v.w;
        }
        __syncthreads();

        float acc[4][4];
#pragma unroll
        for (int i = 0; i < 4; i++)
#pragma unroll
            for (int j = 0; j < 4; j++) acc[i][j] = 0.f;

#pragma unroll 8
        for (int k = 0; k < DIMS; k++) {
            float4 zf = *(const float4*)&zs[k * TPAD + 4 * ty];
            float4 ef = *(const float4*)&es[k * TPAD + 4 * tx];
            float za[4] = {zf.x, zf.y, zf.z, zf.w};
            float ea[4] = {ef.x, ef.y, ef.z, ef.w};
#pragma unroll
            for (int i = 0; i < 4; i++)
#pragma unroll
                for (int j = 0; j < 4; j++)
                    acc[i][j] = fmaf(za[i], ea[j], acc[i][j]);
        }

        // distances in the reference formula/rounding, u64-packed min
#pragma unroll
        for (int i = 0; i < 4; i++) {
            float z2r = z2s[4 * ty + i];
#pragma unroll
            for (int j = 0; j < 4; j++) {
                int code = chunk * TK + 4 * tx + j;
                float t    = __fadd_rn(z2r, g_e2[code]);
                float dist = __fsub_rn(t, __fmul_rn(2.0f, acc[i][j]));
                unsigned long long p =
                    ((unsigned long long)__float_as_uint(dist) << 32) |
                    (unsigned long long)(unsigned)code;
                if (p < best[i]) best[i] = p;
            }
        }
    }

    // ---- reduce candidates across the 16 code-columns per row ----
#pragma unroll
    for (int i = 0; i < 4; i++) cand[(4 * ty + i) * 16 + tx] = best[i];
    __syncthreads();
    if (tid < TM) {
        unsigned long long m = cand[tid * 16];
#pragma unroll
        for (int t = 1; t < 16; t++) {
            unsigned long long v = cand[tid * 16 + t];
            if (v < m) m = v;
        }
        idxs[tid] = (int)(m & 0xffffffffull);
    }
    __syncthreads();

    // ---- epilogue: gather, STE output, loss partial sum ----
    double lsum = 0.0;
    float* outblk = out + (size_t)rowBase * DIMS;
    for (int t = 0; t < TM * DIMS / 256; t++) {
        int e = tid + t * 256;
        int r = e >> 8;            // DIMS == 256
        int d = e & 255;
        float q  = emb[(size_t)idxs[r] * DIMS + d];
        float zv = zs[d * TPAD + r];
        float diff = __fsub_rn(q, zv);
        outblk[e]  = __fadd_rn(zv, diff);   // z + stopgrad(q - z)
        float sq   = __fmul_rn(diff, diff);
        lsum += (double)sq;
    }
    __syncthreads();               // done reading cand as u64
    dred[tid] = lsum;
    __syncthreads();
    for (int s = 128; s > 0; s >>= 1) {
        if (tid < s) dred[tid] += dred[tid + s];
        __syncthreads();
    }
    if (tid == 0) atomicAdd(&g_loss_accum, dred[0]);
}

// ---------------------------------------------------------------------------
// Finalize: write the two (numerically identical) losses
// ---------------------------------------------------------------------------
__global__ void vq_finalize(float* __restrict__ out, int out_size) {
    double mean = g_loss_accum / (double)((size_t)NROWS * DIMS);
    float loss = (float)(0.5 * mean);
    out[out_size - 2] = loss;   // commitment_loss
    out[out_size - 1] = loss;   // emb_loss
}

// ---------------------------------------------------------------------------
extern "C" void kernel_launch(void* const* d_in, const int* in_sizes, int n_in,
                              void* d_out, int out_size) {
    const float* z   = (const float*)d_in[0];
    const float* emb = (const float*)d_in[1];
    // robustness: identify by element count in case metadata order differs
    if (n_in >= 2 && in_sizes[0] == NCODES * DIMS && in_sizes[1] == NROWS * DIMS) {
        emb = (const float*)d_in[0];
        z   = (const float*)d_in[1];
    }
    float* out = (float*)d_out;

    vq_prep<<<(NCODES * 32 + 255) / 256, 256>>>(emb);

    cudaFuncSetAttribute(vq_main, cudaFuncAttributeMaxDynamicSharedMemorySize,
                         SMEM_BYTES);
    vq_main<<<NROWS / TM, 256, SMEM_BYTES>>>(z, emb, out);

    vq_finalize<<<1, 1>>>(out, out_size);
}